// round 1
// baseline (speedup 1.0000x reference)
#include <cuda_runtime.h>
#include <cuda_bf16.h>
#include <math.h>

// Problem constants (match reference)
#define NN 50000
#define MM 800000
#define DD 128
#define EFD 32
#define IN_DIM 290   // 2*128 + 32 + 2
#define TILE_E 32
#define NTHREADS 128
#define KC 32

// Scratch: aggregated messages per node (25.6 MB)
__device__ float g_agg[(size_t)NN * DD];

__device__ __forceinline__ float sigmoidf_fast(float x) {
    return 1.0f / (1.0f + __expf(-x));
}

__global__ void zero_agg_kernel() {
    size_t i = (size_t)blockIdx.x * blockDim.x + threadIdx.x;
    if (i < (size_t)NN * DD) g_agg[i] = 0.0f;
}

// Fused edge kernel: gather edge_input tile, MLP layer1 (msg+att), MLP layer2,
// sigmoid gate, atomic scatter-add into g_agg.
extern "C" __global__ void __launch_bounds__(NTHREADS)
edge_kernel(const float* __restrict__ node_feat,
            const int*   __restrict__ edge,
            const float* __restrict__ edge_feat,
            const float* __restrict__ node_attr,   // [2][N]
            const float* __restrict__ edge_attr,   // [N][128]
            const float* __restrict__ msg_w1, const float* __restrict__ msg_b1,
            const float* __restrict__ msg_w2, const float* __restrict__ msg_b2,
            const float* __restrict__ att_w1, const float* __restrict__ att_b1,
            const float* __restrict__ att_w2, const float* __restrict__ att_b2,
            int M_, int N_)
{
    extern __shared__ float smem[];
    float* in_s = smem;                       // [TILE_E][IN_DIM]
    float* wm_s = in_s + TILE_E * IN_DIM;     // [KC][128]
    float* wa_s = wm_s + KC * 128;            // [KC][128]
    float* h_s  = wa_s + KC * 128;            // [TILE_E][128]
    float* a_s  = h_s  + TILE_E * 128;        // [TILE_E][128]
    __shared__ int src_s[TILE_E];
    __shared__ int dst_s[TILE_E];

    const int tid = threadIdx.x;
    const int tc  = tid & 31;   // col lane
    const int te  = tid >> 5;   // edge group (warp id)
    const int e0  = blockIdx.x * TILE_E;

    // ---- load edge endpoints ----
    if (tid < TILE_E) {
        int ge = e0 + tid;
        int s = 0, d = 0;
        if (ge < M_) { s = edge[2 * ge]; d = edge[2 * ge + 1]; }
        src_s[tid] = s;
        dst_s[tid] = d;
    }
    __syncthreads();

    // ---- gather edge_input tile [TILE_E][IN_DIM] ----
    for (int idx = tid; idx < TILE_E * IN_DIM; idx += NTHREADS) {
        int e = idx / IN_DIM;
        int k = idx - e * IN_DIM;
        int ge = e0 + e;
        float v = 0.0f;
        if (ge < M_) {
            int s = src_s[e], d = dst_s[e];
            if (k < 128) {
                v = node_feat[s * 128 + k] - node_feat[d * 128 + k];
            } else if (k < 160) {
                v = edge_feat[(size_t)ge * EFD + (k - 128)];
            } else if (k < 288) {
                int kk = k - 160;
                v = edge_attr[s * 128 + kk] - edge_attr[d * 128 + kk];
            } else {
                int a = k - 288;
                v = node_attr[a * N_ + s] - node_attr[a * N_ + d];
            }
        }
        in_s[e * IN_DIM + k] = v;
    }
    __syncthreads();

    const float* inp = in_s + (te * 8) * IN_DIM;

    // ================= Phase A: layer 1 (both branches) =================
    float accM[8][4], accA[8][4];
    #pragma unroll
    for (int i = 0; i < 8; ++i)
        #pragma unroll
        for (int j = 0; j < 4; ++j) { accM[i][j] = 0.f; accA[i][j] = 0.f; }

    for (int k0 = 0; k0 < IN_DIM; k0 += KC) {
        int kc = IN_DIM - k0; if (kc > KC) kc = KC;
        for (int idx = tid; idx < kc * 128; idx += NTHREADS) {
            wm_s[idx] = msg_w1[k0 * 128 + idx];
            wa_s[idx] = att_w1[k0 * 128 + idx];
        }
        __syncthreads();
        #pragma unroll 4
        for (int kk = 0; kk < kc; ++kk) {
            float wvm[4], wva[4];
            #pragma unroll
            for (int j = 0; j < 4; ++j) {
                wvm[j] = wm_s[kk * 128 + tc + 32 * j];
                wva[j] = wa_s[kk * 128 + tc + 32 * j];
            }
            int kabs = k0 + kk;
            #pragma unroll
            for (int i = 0; i < 8; ++i) {
                float xv = inp[i * IN_DIM + kabs];
                #pragma unroll
                for (int j = 0; j < 4; ++j) {
                    accM[i][j] = fmaf(xv, wvm[j], accM[i][j]);
                    accA[i][j] = fmaf(xv, wva[j], accA[i][j]);
                }
            }
        }
        __syncthreads();
    }

    // bias + relu, store to shared
    #pragma unroll
    for (int j = 0; j < 4; ++j) {
        int c = tc + 32 * j;
        float bm = msg_b1[c];
        float ba = att_b1[c];
        #pragma unroll
        for (int i = 0; i < 8; ++i) {
            h_s[(te * 8 + i) * 128 + c] = fmaxf(accM[i][j] + bm, 0.0f);
            a_s[(te * 8 + i) * 128 + c] = fmaxf(accA[i][j] + ba, 0.0f);
        }
    }
    __syncthreads();

    // ================= Phase B: layer 2 (both branches) =================
    #pragma unroll
    for (int i = 0; i < 8; ++i)
        #pragma unroll
        for (int j = 0; j < 4; ++j) { accM[i][j] = 0.f; accA[i][j] = 0.f; }

    const float* hp = h_s + (te * 8) * 128;
    const float* ap = a_s + (te * 8) * 128;

    for (int k0 = 0; k0 < 128; k0 += KC) {
        for (int idx = tid; idx < KC * 128; idx += NTHREADS) {
            wm_s[idx] = msg_w2[k0 * 128 + idx];
            wa_s[idx] = att_w2[k0 * 128 + idx];
        }
        __syncthreads();
        #pragma unroll 4
        for (int kk = 0; kk < KC; ++kk) {
            float wvm[4], wva[4];
            #pragma unroll
            for (int j = 0; j < 4; ++j) {
                wvm[j] = wm_s[kk * 128 + tc + 32 * j];
                wva[j] = wa_s[kk * 128 + tc + 32 * j];
            }
            int kabs = k0 + kk;
            #pragma unroll
            for (int i = 0; i < 8; ++i) {
                float hv = hp[i * 128 + kabs];
                float av = ap[i * 128 + kabs];
                #pragma unroll
                for (int j = 0; j < 4; ++j) {
                    accM[i][j] = fmaf(hv, wvm[j], accM[i][j]);
                    accA[i][j] = fmaf(av, wva[j], accA[i][j]);
                }
            }
        }
        __syncthreads();
    }

    // bias, sigmoid gate, scatter-add
    #pragma unroll
    for (int i = 0; i < 8; ++i) {
        int ge = e0 + te * 8 + i;
        if (ge >= M_) continue;
        int d = dst_s[te * 8 + i];
        #pragma unroll
        for (int j = 0; j < 4; ++j) {
            int c = tc + 32 * j;
            float msg = accM[i][j] + msg_b2[c];
            float att = sigmoidf_fast(accA[i][j] + att_b2[c]);
            atomicAdd(&g_agg[(size_t)d * 128 + c], msg * att);
        }
    }
}

// GRU update per node.
extern "C" __global__ void __launch_bounds__(128)
gru_kernel(const float* __restrict__ node_feat,
           const float* __restrict__ w_ih,  // [384][128]
           const float* __restrict__ w_hh,  // [384][128]
           const float* __restrict__ b_ih,  // [384]
           const float* __restrict__ b_hh,  // [384]
           float* __restrict__ out, int N_)
{
    __shared__ __align__(16) float agg_s[8 * 128];
    __shared__ __align__(16) float st_s[8 * 128];
    __shared__ float gi_s[8 * 384];
    __shared__ float gh_s[8 * 384];

    const int tid = threadIdx.x;
    const int n0 = blockIdx.x * 8;

    for (int idx = tid; idx < 8 * 128; idx += 128) {
        int n = idx >> 7, c = idx & 127;
        int gn = n0 + n;
        float av = 0.f, sv = 0.f;
        if (gn < N_) {
            av = g_agg[(size_t)gn * 128 + c];
            sv = node_feat[(size_t)gn * 128 + c];
        }
        agg_s[idx] = av;
        st_s[idx]  = sv;
    }
    __syncthreads();

    for (int idx = tid; idx < 8 * 384; idx += 128) {
        int n = idx / 384;
        int j = idx - n * 384;
        const float4* wi4 = (const float4*)(w_ih + j * 128);
        const float4* wh4 = (const float4*)(w_hh + j * 128);
        const float4* x4  = (const float4*)(agg_s + n * 128);
        const float4* s4  = (const float4*)(st_s + n * 128);
        float si = 0.f, sh = 0.f;
        #pragma unroll 8
        for (int k = 0; k < 32; ++k) {
            float4 a = x4[k], b = wi4[k];
            si += a.x * b.x + a.y * b.y + a.z * b.z + a.w * b.w;
            float4 c = s4[k], d = wh4[k];
            sh += c.x * d.x + c.y * d.y + c.z * d.z + c.w * d.w;
        }
        gi_s[idx] = si + b_ih[j];
        gh_s[idx] = sh + b_hh[j];
    }
    __syncthreads();

    for (int idx = tid; idx < 8 * 128; idx += 128) {
        int n = idx >> 7, c = idx & 127;
        int gn = n0 + n;
        if (gn >= N_) continue;
        float ir = gi_s[n * 384 + c];
        float iz = gi_s[n * 384 + 128 + c];
        float in_ = gi_s[n * 384 + 256 + c];
        float hr = gh_s[n * 384 + c];
        float hz = gh_s[n * 384 + 128 + c];
        float hn = gh_s[n * 384 + 256 + c];
        float r = sigmoidf_fast(ir + hr);
        float z = sigmoidf_fast(iz + hz);
        float nv = tanhf(in_ + r * hn);
        out[(size_t)gn * 128 + c] = (1.0f - z) * nv + z * st_s[idx];
    }
}

extern "C" void kernel_launch(void* const* d_in, const int* in_sizes, int n_in,
                              void* d_out, int out_size)
{
    const float* node_feat = (const float*)d_in[0];
    const int*   edge      = (const int*)  d_in[1];
    const float* edge_feat = (const float*)d_in[2];
    const float* node_attr = (const float*)d_in[3];
    const float* edge_attr = (const float*)d_in[4];
    const float* msg_w1    = (const float*)d_in[5];
    const float* msg_b1    = (const float*)d_in[6];
    const float* msg_w2    = (const float*)d_in[7];
    const float* msg_b2    = (const float*)d_in[8];
    const float* att_w1    = (const float*)d_in[9];
    const float* att_b1    = (const float*)d_in[10];
    const float* att_w2    = (const float*)d_in[11];
    const float* att_b2    = (const float*)d_in[12];
    const float* gru_w_ih  = (const float*)d_in[13];
    const float* gru_w_hh  = (const float*)d_in[14];
    const float* gru_b_ih  = (const float*)d_in[15];
    const float* gru_b_hh  = (const float*)d_in[16];
    float* out = (float*)d_out;

    int N_ = in_sizes[0] / DD;
    int M_ = in_sizes[1] / 2;

    // Dynamic smem for edge kernel
    size_t smem_bytes = (size_t)(TILE_E * IN_DIM + 2 * KC * 128 + 2 * TILE_E * 128) * sizeof(float);
    cudaFuncSetAttribute(edge_kernel, cudaFuncAttributeMaxDynamicSharedMemorySize, (int)smem_bytes);

    size_t tot = (size_t)NN * DD;
    zero_agg_kernel<<<(int)((tot + 255) / 256), 256>>>();

    int eblocks = (M_ + TILE_E - 1) / TILE_E;
    edge_kernel<<<eblocks, NTHREADS, smem_bytes>>>(
        node_feat, edge, edge_feat, node_attr, edge_attr,
        msg_w1, msg_b1, msg_w2, msg_b2,
        att_w1, att_b1, att_w2, att_b2, M_, N_);

    int gblocks = (N_ + 7) / 8;
    gru_kernel<<<gblocks, 128>>>(node_feat, gru_w_ih, gru_w_hh, gru_b_ih, gru_b_hh, out, N_);
}

// round 3
// speedup vs baseline: 1.2156x; 1.2156x over previous
#include <cuda_runtime.h>
#include <cuda_bf16.h>
#include <math.h>

#define NN 50000
#define DD 128
#define EFD 32
#define IN_DIM 290
#define KPAD 320         // IN_DIM padded to 10 slabs of 32
#define TILE_E 128
#define ETHREADS 256

// Scratch: aggregated messages per node
__device__ float g_agg[(size_t)NN * DD];

__device__ __forceinline__ float sigmoidf_fast(float x) {
    return 1.0f / (1.0f + __expf(-x));
}

__device__ __forceinline__ unsigned f2tf32(float f) {
    unsigned u;
    asm("cvt.rna.tf32.f32 %0, %1;" : "=r"(u) : "f"(f));
    return u;
}

__device__ __forceinline__ void mma_tf32(float c[4], const unsigned a[4], const unsigned b[2]) {
    asm volatile(
        "mma.sync.aligned.m16n8k8.row.col.f32.tf32.tf32.f32 "
        "{%0,%1,%2,%3}, {%4,%5,%6,%7}, {%8,%9}, {%0,%1,%2,%3};"
        : "+f"(c[0]), "+f"(c[1]), "+f"(c[2]), "+f"(c[3])
        : "r"(a[0]), "r"(a[1]), "r"(a[2]), "r"(a[3]), "r"(b[0]), "r"(b[1]));
}

__global__ void zero_agg_kernel() {
    size_t i = (size_t)blockIdx.x * blockDim.x + threadIdx.x;
    if (i < (size_t)NN * DD) g_agg[i] = 0.0f;
}

// Shared memory layout (uint32 units):
//   ws  : [0, 8448)            weight slab [32][264]
//   hs  : [8448, 25344)        H (relu msg layer1) [128][132]   (xs aliases front)
//   as_ : [25344, 42240)       A (relu att layer1) [128][132]
#define WS_OFF 0
#define HS_OFF 8448
#define AS_OFF 25344
#define SMEM_U32 42240
#define LDW 264
#define LDX 36
#define LDH 132

extern "C" __global__ void __launch_bounds__(ETHREADS, 1)
edge_kernel(const float* __restrict__ node_feat,
            const int*   __restrict__ edge,
            const float* __restrict__ edge_feat,
            const float* __restrict__ node_attr,   // [2][N]
            const float* __restrict__ edge_attr,   // [N][128]
            const float* __restrict__ msg_w1, const float* __restrict__ msg_b1,
            const float* __restrict__ msg_w2, const float* __restrict__ msg_b2,
            const float* __restrict__ att_w1, const float* __restrict__ att_b1,
            const float* __restrict__ att_w2, const float* __restrict__ att_b2,
            int M_, int N_)
{
    extern __shared__ unsigned smem[];
    unsigned* ws  = smem + WS_OFF;
    unsigned* hs  = smem + HS_OFF;
    unsigned* as_ = smem + AS_OFF;
    unsigned* xs  = smem + HS_OFF;  // alias (phase 1 only)

    __shared__ int src_s[TILE_E];
    __shared__ int dst_s[TILE_E];

    const int tid  = threadIdx.x;
    const int lane = tid & 31;
    const int wid  = tid >> 5;
    const int g    = lane >> 2;     // 0..7
    const int tg   = lane & 3;      // 0..3
    const int wm   = wid & 3;       // row-warp 0..3
    const int wn   = wid >> 2;      // col-warp 0..1
    const int r0w  = 32 * wm;
    const int c0w  = 64 * wn;
    const int e0   = blockIdx.x * TILE_E;

    // ---- edge endpoints ----
    if (tid < TILE_E) {
        int ge = e0 + tid;
        int s = 0, d = 0;
        if (ge < M_) { s = edge[2 * ge]; d = edge[2 * ge + 1]; }
        src_s[tid] = s;
        dst_s[tid] = d;
    }
    __syncthreads();

    float accM[2][8][4], accA[2][8][4];
    #pragma unroll
    for (int mt = 0; mt < 2; ++mt)
        #pragma unroll
        for (int nt = 0; nt < 8; ++nt)
            #pragma unroll
            for (int c = 0; c < 4; ++c) { accM[mt][nt][c] = 0.f; accA[mt][nt][c] = 0.f; }

    const int rgrp = tid >> 5; // 8 row-groups for gather

    // =================== Phase 1: layer-1 GEMM over K slabs ===================
    for (int k0 = 0; k0 < KPAD; k0 += 32) {
        // gather X slab [128][32]
        if (k0 < 128) {
            for (int r = rgrp; r < TILE_E; r += 8) {
                int s = src_s[r], d = dst_s[r];
                float v = node_feat[s * 128 + k0 + lane] - node_feat[d * 128 + k0 + lane];
                xs[r * LDX + lane] = f2tf32(v);
            }
        } else if (k0 == 128) {
            for (int r = rgrp; r < TILE_E; r += 8) {
                int ge = e0 + r;
                float v = (ge < M_) ? edge_feat[(size_t)ge * EFD + lane] : 0.f;
                xs[r * LDX + lane] = f2tf32(v);
            }
        } else if (k0 < 288) {
            int kk = k0 - 160;
            for (int r = rgrp; r < TILE_E; r += 8) {
                int s = src_s[r], d = dst_s[r];
                float v = edge_attr[s * 128 + kk + lane] - edge_attr[d * 128 + kk + lane];
                xs[r * LDX + lane] = f2tf32(v);
            }
        } else {
            for (int r = rgrp; r < TILE_E; r += 8) {
                float v = 0.f;
                if (lane < 2) {
                    int s = src_s[r], d = dst_s[r];
                    v = node_attr[lane * N_ + s] - node_attr[lane * N_ + d];
                }
                xs[r * LDX + lane] = f2tf32(v);
            }
        }
        // load weight slab [32][256] = msg_w1 | att_w1
        for (int idx = tid; idx < 32 * 256; idx += ETHREADS) {
            int kk = idx >> 8;
            int c  = idx & 255;
            int kg = k0 + kk;
            float v = 0.f;
            if (kg < IN_DIM)
                v = (c < 128) ? msg_w1[kg * 128 + c] : att_w1[kg * 128 + (c - 128)];
            ws[kk * LDW + c] = f2tf32(v);
        }
        __syncthreads();

        #pragma unroll
        for (int ks = 0; ks < 4; ++ks) {
            const int kl = 8 * ks;
            unsigned a[2][4];
            #pragma unroll
            for (int mt = 0; mt < 2; ++mt) {
                int row = r0w + 16 * mt + g;
                a[mt][0] = xs[row * LDX + kl + tg];
                a[mt][1] = xs[(row + 8) * LDX + kl + tg];
                a[mt][2] = xs[row * LDX + kl + tg + 4];
                a[mt][3] = xs[(row + 8) * LDX + kl + tg + 4];
            }
            #pragma unroll
            for (int nt = 0; nt < 8; ++nt) {
                int cb = c0w + 8 * nt + g;
                unsigned bm[2], ba[2];
                bm[0] = ws[(kl + tg) * LDW + cb];
                bm[1] = ws[(kl + tg + 4) * LDW + cb];
                ba[0] = ws[(kl + tg) * LDW + cb + 128];
                ba[1] = ws[(kl + tg + 4) * LDW + cb + 128];
                mma_tf32(accM[0][nt], a[0], bm);
                mma_tf32(accM[1][nt], a[1], bm);
                mma_tf32(accA[0][nt], a[0], ba);
                mma_tf32(accA[1][nt], a[1], ba);
            }
        }
        __syncthreads();
    }

    // ---- epilogue 1: bias + relu -> hs / as_ (tf32) ----
    #pragma unroll
    for (int mt = 0; mt < 2; ++mt)
        #pragma unroll
        for (int nt = 0; nt < 8; ++nt)
            #pragma unroll
            for (int c = 0; c < 4; ++c) {
                int row = r0w + 16 * mt + g + 8 * (c >> 1);
                int col = c0w + 8 * nt + 2 * tg + (c & 1);
                float hm = fmaxf(accM[mt][nt][c] + msg_b1[col], 0.f);
                float ha = fmaxf(accA[mt][nt][c] + att_b1[col], 0.f);
                hs[row * LDH + col]  = f2tf32(hm);
                as_[row * LDH + col] = f2tf32(ha);
            }
    __syncthreads();

    // =================== Phase 2: layer-2 GEMM ===================
    #pragma unroll
    for (int mt = 0; mt < 2; ++mt)
        #pragma unroll
        for (int nt = 0; nt < 8; ++nt)
            #pragma unroll
            for (int c = 0; c < 4; ++c) { accM[mt][nt][c] = 0.f; accA[mt][nt][c] = 0.f; }

    for (int k0 = 0; k0 < 128; k0 += 32) {
        for (int idx = tid; idx < 32 * 256; idx += ETHREADS) {
            int kk = idx >> 8;
            int c  = idx & 255;
            int kg = k0 + kk;
            float v = (c < 128) ? msg_w2[kg * 128 + c] : att_w2[kg * 128 + (c - 128)];
            ws[kk * LDW + c] = f2tf32(v);
        }
        __syncthreads();

        #pragma unroll
        for (int ks = 0; ks < 4; ++ks) {
            const int kl = k0 + 8 * ks;
            unsigned ah[2][4], aa[2][4];
            #pragma unroll
            for (int mt = 0; mt < 2; ++mt) {
                int row = r0w + 16 * mt + g;
                ah[mt][0] = hs[row * LDH + kl + tg];
                ah[mt][1] = hs[(row + 8) * LDH + kl + tg];
                ah[mt][2] = hs[row * LDH + kl + tg + 4];
                ah[mt][3] = hs[(row + 8) * LDH + kl + tg + 4];
                aa[mt][0] = as_[row * LDH + kl + tg];
                aa[mt][1] = as_[(row + 8) * LDH + kl + tg];
                aa[mt][2] = as_[row * LDH + kl + tg + 4];
                aa[mt][3] = as_[(row + 8) * LDH + kl + tg + 4];
            }
            int klw = 8 * ks;
            #pragma unroll
            for (int nt = 0; nt < 8; ++nt) {
                int cb = c0w + 8 * nt + g;
                unsigned bm[2], ba[2];
                bm[0] = ws[(klw + tg) * LDW + cb];
                bm[1] = ws[(klw + tg + 4) * LDW + cb];
                ba[0] = ws[(klw + tg) * LDW + cb + 128];
                ba[1] = ws[(klw + tg + 4) * LDW + cb + 128];
                mma_tf32(accM[0][nt], ah[0], bm);
                mma_tf32(accM[1][nt], ah[1], bm);
                mma_tf32(accA[0][nt], aa[0], ba);
                mma_tf32(accA[1][nt], aa[1], ba);
            }
        }
        __syncthreads();
    }

    // ---- epilogue 2: bias, sigmoid gate, atomic scatter-add ----
    #pragma unroll
    for (int mt = 0; mt < 2; ++mt) {
        #pragma unroll
        for (int c = 0; c < 4; ++c) {
            int row = r0w + 16 * mt + g + 8 * (c >> 1);
            int ge = e0 + row;
            if (ge >= M_) continue;
            int d = dst_s[row];
            float* dstp = g_agg + (size_t)d * 128;
            #pragma unroll
            for (int nt = 0; nt < 8; ++nt) {
                int col = c0w + 8 * nt + 2 * tg + (c & 1);
                float msg = accM[mt][nt][c] + msg_b2[col];
                float att = sigmoidf_fast(accA[mt][nt][c] + att_b2[col]);
                atomicAdd(dstp + col, msg * att);
            }
        }
    }
}

// GRU update per node.
extern "C" __global__ void __launch_bounds__(128)
gru_kernel(const float* __restrict__ node_feat,
           const float* __restrict__ w_ih,  // [384][128]
           const float* __restrict__ w_hh,  // [384][128]
           const float* __restrict__ b_ih,
           const float* __restrict__ b_hh,
           float* __restrict__ out, int N_)
{
    __shared__ __align__(16) float agg_s[8 * 128];
    __shared__ __align__(16) float st_s[8 * 128];
    __shared__ float gi_s[8 * 384];
    __shared__ float gh_s[8 * 384];

    const int tid = threadIdx.x;
    const int n0 = blockIdx.x * 8;

    for (int idx = tid; idx < 8 * 128; idx += 128) {
        int n = idx >> 7, c = idx & 127;
        int gn = n0 + n;
        float av = 0.f, sv = 0.f;
        if (gn < N_) {
            av = g_agg[(size_t)gn * 128 + c];
            sv = node_feat[(size_t)gn * 128 + c];
        }
        agg_s[idx] = av;
        st_s[idx]  = sv;
    }
    __syncthreads();

    for (int idx = tid; idx < 8 * 384; idx += 128) {
        int n = idx / 384;
        int j = idx - n * 384;
        const float4* wi4 = (const float4*)(w_ih + j * 128);
        const float4* wh4 = (const float4*)(w_hh + j * 128);
        const float4* x4  = (const float4*)(agg_s + n * 128);
        const float4* s4  = (const float4*)(st_s + n * 128);
        float si = 0.f, sh = 0.f;
        #pragma unroll 8
        for (int k = 0; k < 32; ++k) {
            float4 a = x4[k], b = wi4[k];
            si += a.x * b.x + a.y * b.y + a.z * b.z + a.w * b.w;
            float4 c = s4[k], d = wh4[k];
            sh += c.x * d.x + c.y * d.y + c.z * d.z + c.w * d.w;
        }
        gi_s[idx] = si + b_ih[j];
        gh_s[idx] = sh + b_hh[j];
    }
    __syncthreads();

    for (int idx = tid; idx < 8 * 128; idx += 128) {
        int n = idx >> 7, c = idx & 127;
        int gn = n0 + n;
        if (gn >= N_) continue;
        float ir = gi_s[n * 384 + c];
        float iz = gi_s[n * 384 + 128 + c];
        float in_ = gi_s[n * 384 + 256 + c];
        float hr = gh_s[n * 384 + c];
        float hz = gh_s[n * 384 + 128 + c];
        float hn = gh_s[n * 384 + 256 + c];
        float r = sigmoidf_fast(ir + hr);
        float z = sigmoidf_fast(iz + hz);
        float nv = tanhf(in_ + r * hn);
        out[(size_t)gn * 128 + c] = (1.0f - z) * nv + z * st_s[idx];
    }
}

extern "C" void kernel_launch(void* const* d_in, const int* in_sizes, int n_in,
                              void* d_out, int out_size)
{
    const float* node_feat = (const float*)d_in[0];
    const int*   edge      = (const int*)  d_in[1];
    const float* edge_feat = (const float*)d_in[2];
    const float* node_attr = (const float*)d_in[3];
    const float* edge_attr = (const float*)d_in[4];
    const float* msg_w1    = (const float*)d_in[5];
    const float* msg_b1    = (const float*)d_in[6];
    const float* msg_w2    = (const float*)d_in[7];
    const float* msg_b2    = (const float*)d_in[8];
    const float* att_w1    = (const float*)d_in[9];
    const float* att_b1    = (const float*)d_in[10];
    const float* att_w2    = (const float*)d_in[11];
    const float* att_b2    = (const float*)d_in[12];
    const float* gru_w_ih  = (const float*)d_in[13];
    const float* gru_w_hh  = (const float*)d_in[14];
    const float* gru_b_ih  = (const float*)d_in[15];
    const float* gru_b_hh  = (const float*)d_in[16];
    float* out = (float*)d_out;

    int N_ = in_sizes[0] / DD;
    int M_ = in_sizes[1] / 2;

    size_t smem_bytes = (size_t)SMEM_U32 * 4;
    cudaFuncSetAttribute(edge_kernel, cudaFuncAttributeMaxDynamicSharedMemorySize, (int)smem_bytes);

    size_t tot = (size_t)NN * DD;
    zero_agg_kernel<<<(int)((tot + 255) / 256), 256>>>();

    int eblocks = (M_ + TILE_E - 1) / TILE_E;
    edge_kernel<<<eblocks, ETHREADS, smem_bytes>>>(
        node_feat, edge, edge_feat, node_attr, edge_attr,
        msg_w1, msg_b1, msg_w2, msg_b2,
        att_w1, att_b1, att_w2, att_b2, M_, N_);

    int gblocks = (N_ + 7) / 8;
    gru_kernel<<<gblocks, 128>>>(node_feat, gru_w_ih, gru_w_hh, gru_b_ih, gru_b_hh, out, N_);
}

// round 7
// speedup vs baseline: 1.9752x; 1.6248x over previous
#include <cuda_runtime.h>
#include <cstdint>
#include <math.h>

#define DD 128
#define ETHREADS 256

// Device scratch
__device__ float g_agg[(size_t)50000 * 128];
__device__ float g_P[(size_t)50000 * 256];

__device__ __forceinline__ float sigmoidf_fast(float x) {
    return 1.0f / (1.0f + __expf(-x));
}
__device__ __forceinline__ unsigned f2tf32(float f) {
    unsigned u;
    asm("cvt.rna.tf32.f32 %0, %1;" : "=r"(u) : "f"(f));
    return u;
}
__device__ __forceinline__ void mma_tf32(float c[4], const unsigned a[4], const unsigned b[2]) {
    asm volatile(
        "mma.sync.aligned.m16n8k8.row.col.f32.tf32.tf32.f32 "
        "{%0,%1,%2,%3}, {%4,%5,%6,%7}, {%8,%9}, {%0,%1,%2,%3};"
        : "+f"(c[0]), "+f"(c[1]), "+f"(c[2]), "+f"(c[3])
        : "r"(a[0]), "r"(a[1]), "r"(a[2]), "r"(a[3]), "r"(b[0]), "r"(b[1]));
}

__global__ void zero_agg_kernel() {
    size_t i = (size_t)blockIdx.x * blockDim.x + threadIdx.x;
    if (i < (size_t)50000 * 128) g_agg[i] = 0.0f;
}

// ===================== Node projection kernel =====================
// P[n][c] = state[n]@W1[0:128] + eattr[n]@W1[160:288] + na0[n]*W1[288] + na1[n]*W1[289]
// c<128 -> msg_w1 columns, c>=128 -> att_w1 columns.
#define NLDA 36
#define NLDW 264
extern "C" __global__ void __launch_bounds__(ETHREADS)
nodeproj_kernel(const float* __restrict__ node_feat,
                const float* __restrict__ node_attr,   // [2][N]
                const float* __restrict__ edge_attr,   // [N][128]
                const float* __restrict__ msg_w1,
                const float* __restrict__ att_w1,
                int N_)
{
    __shared__ uint32_t xs[64 * NLDA];
    __shared__ uint32_t ws[32 * NLDW];
    __shared__ float wna[2][256];

    const int tid  = threadIdx.x;
    const int lane = tid & 31;
    const int wid  = tid >> 5;
    const int g    = lane >> 2;
    const int tg   = lane & 3;
    const int mg   = wid >> 2;       // 0..1 -> rows 32*mg
    const int ng   = wid & 3;        // 0..3 -> cols 64*ng
    const int n0   = blockIdx.x * 64;

    // preload na weight rows (288, 289)
    for (int c = tid; c < 256; c += ETHREADS) {
        const float* w1 = (c < 128) ? msg_w1 : att_w1;
        int cc = c & 127;
        wna[0][c] = w1[288 * 128 + cc];
        wna[1][c] = w1[289 * 128 + cc];
    }

    float acc[2][8][4];
    #pragma unroll
    for (int mt = 0; mt < 2; ++mt)
        #pragma unroll
        for (int nt = 0; nt < 8; ++nt)
            #pragma unroll
            for (int c = 0; c < 4; ++c) acc[mt][nt][c] = 0.f;

    for (int s = 0; s < 8; ++s) {
        const int k0 = 32 * s;
        // A slab [64][32]
        for (int idx = tid; idx < 64 * 32; idx += ETHREADS) {
            int row = idx >> 5, kk = idx & 31;
            int n = n0 + row;
            float v = 0.f;
            if (n < N_) {
                int k = k0 + kk;
                v = (k < 128) ? node_feat[(size_t)n * 128 + k]
                              : edge_attr[(size_t)n * 128 + (k - 128)];
            }
            xs[row * NLDA + kk] = f2tf32(v);
        }
        // W slab [32][256]
        for (int idx = tid; idx < 32 * 256; idx += ETHREADS) {
            int kk = idx >> 8, c = idx & 255;
            int k = k0 + kk;
            int wrow = (k < 128) ? k : (k + 32);   // 160 + (k-128)
            float v = (c < 128) ? msg_w1[wrow * 128 + c] : att_w1[wrow * 128 + (c - 128)];
            ws[kk * NLDW + c] = f2tf32(v);
        }
        __syncthreads();
        #pragma unroll
        for (int ks = 0; ks < 4; ++ks) {
            const int kl = 8 * ks;
            unsigned a[2][4];
            #pragma unroll
            for (int mt = 0; mt < 2; ++mt) {
                int row = 32 * mg + 16 * mt + g;
                a[mt][0] = xs[row * NLDA + kl + tg];
                a[mt][1] = xs[(row + 8) * NLDA + kl + tg];
                a[mt][2] = xs[row * NLDA + kl + tg + 4];
                a[mt][3] = xs[(row + 8) * NLDA + kl + tg + 4];
            }
            #pragma unroll
            for (int nt = 0; nt < 8; ++nt) {
                int cb = 64 * ng + 8 * nt + g;
                unsigned b[2];
                b[0] = ws[(kl + tg) * NLDW + cb];
                b[1] = ws[(kl + tg + 4) * NLDW + cb];
                mma_tf32(acc[0][nt], a[0], b);
                mma_tf32(acc[1][nt], a[1], b);
            }
        }
        __syncthreads();
    }

    // epilogue: add node_attr rank-2 terms and store
    #pragma unroll
    for (int mt = 0; mt < 2; ++mt)
        #pragma unroll
        for (int c = 0; c < 4; ++c) {
            int r = 32 * mg + 16 * mt + g + 8 * (c >> 1);
            int n = n0 + r;
            if (n >= N_) continue;
            float na0 = node_attr[n];
            float na1 = node_attr[N_ + n];
            #pragma unroll
            for (int nt = 0; nt < 8; ++nt) {
                int col = 64 * ng + 8 * nt + 2 * tg + (c & 1);
                g_P[(size_t)n * 256 + col] =
                    acc[mt][nt][c] + na0 * wna[0][col] + na1 * wna[1][col];
            }
        }
}

// ===================== Edge kernel (persistent) =====================
// smem (u32 units):
//   w2s  [0, 32768)           W2 cat [128][256]  (XOR swizzled)
//   wefs [32768, 40960)       W_ef   [32][256]   (XOR swizzled)
//   pre  [40960, 57600)       [64][260]  gather / H / exchange buffer
//   sd   [57600, 57728)       src[64] | dst[64]
#define LDP 260
#define W2_OFF  0
#define WEF_OFF 32768
#define PRE_OFF 40960
#define SD_OFF  57600
#define EDGE_SMEM_U32 57728
#define EDGE_SMEM_BYTES (EDGE_SMEM_U32 * 4)

extern "C" __global__ void __launch_bounds__(ETHREADS, 1)
edge_kernel(const int*   __restrict__ edge,
            const float* __restrict__ edge_feat,
            const float* __restrict__ msg_w1, const float* __restrict__ msg_b1,
            const float* __restrict__ msg_w2, const float* __restrict__ msg_b2,
            const float* __restrict__ att_w1, const float* __restrict__ att_b1,
            const float* __restrict__ att_w2, const float* __restrict__ att_b2,
            int M_)
{
    extern __shared__ uint32_t sm[];
    uint32_t* w2s  = sm + W2_OFF;
    uint32_t* wefs = sm + WEF_OFF;
    uint32_t* pre  = sm + PRE_OFF;
    float*    pref = (float*)pre;
    int*      sd   = (int*)(sm + SD_OFF);

    const int tid  = threadIdx.x;
    const int lane = tid & 31;
    const int wid  = tid >> 5;
    const int g    = lane >> 2;
    const int tg   = lane & 3;
    const int mg   = wid >> 2;        // rows 32*mg
    const int ng   = wid & 3;         // cols 64*ng
    const int br   = ng >> 1;         // branch: 0=msg, 1=att
    const int koff = br << 7;

    // ---- load all weights once (XOR swizzle: addr = k*256 + (n ^ ((k&3)<<3))) ----
    for (int idx = tid; idx < 128 * 256; idx += ETHREADS) {
        int k = idx >> 8, n = idx & 255;
        float v = (n < 128) ? msg_w2[k * 128 + n] : att_w2[k * 128 + (n - 128)];
        w2s[(k << 8) + (n ^ ((k & 3) << 3))] = f2tf32(v);
    }
    for (int idx = tid; idx < 32 * 256; idx += ETHREADS) {
        int k = idx >> 8, n = idx & 255;
        float v = (n < 128) ? msg_w1[(128 + k) * 128 + n] : att_w1[(128 + k) * 128 + (n - 128)];
        wefs[(k << 8) + (n ^ ((k & 3) << 3))] = f2tf32(v);
    }
    __syncthreads();

    const int ntiles = (M_ + 63) >> 6;
    for (int t = blockIdx.x; t < ntiles; t += gridDim.x) {
        const int e0 = t << 6;

        // ---- endpoints + EF gather into pre[.][0..31] ----
        if (tid < 64) {
            int ge = e0 + tid;
            int s = 0, d = 0;
            if (ge < M_) { s = edge[2 * ge]; d = edge[2 * ge + 1]; }
            sd[tid] = s;
            sd[64 + tid] = d;
        }
        for (int idx = tid; idx < 64 * 32; idx += ETHREADS) {
            int row = idx >> 5, kk = idx & 31;
            int ge = e0 + row;
            float v = (ge < M_) ? edge_feat[(size_t)ge * 32 + kk] : 0.f;
            pre[row * LDP + kk] = f2tf32(v);
        }
        __syncthreads();

        // ---- EF mma (K=32) ----
        float acc[2][8][4];
        #pragma unroll
        for (int mt = 0; mt < 2; ++mt)
            #pragma unroll
            for (int nt = 0; nt < 8; ++nt)
                #pragma unroll
                for (int c = 0; c < 4; ++c) acc[mt][nt][c] = 0.f;

        #pragma unroll
        for (int ks = 0; ks < 4; ++ks) {
            const int kl = 8 * ks;
            unsigned a[2][4];
            #pragma unroll
            for (int mt = 0; mt < 2; ++mt) {
                int row = 32 * mg + 16 * mt + g;
                a[mt][0] = pre[row * LDP + kl + tg];
                a[mt][1] = pre[(row + 8) * LDP + kl + tg];
                a[mt][2] = pre[row * LDP + kl + tg + 4];
                a[mt][3] = pre[(row + 8) * LDP + kl + tg + 4];
            }
            #pragma unroll
            for (int nt = 0; nt < 8; ++nt) {
                int n = 64 * ng + 8 * nt + g;
                unsigned b[2];
                b[0] = wefs[((kl + tg) << 8) + (n ^ (tg << 3))];
                b[1] = wefs[((kl + tg + 4) << 8) + (n ^ (tg << 3))];
                mma_tf32(acc[0][nt], a[0], b);
                mma_tf32(acc[1][nt], a[1], b);
            }
        }
        __syncthreads();   // all EF A-reads done before overwrite

        // ---- P-diff gather (float4) ----
        for (int idx = tid; idx < 64 * 64; idx += ETHREADS) {
            int row = idx >> 6, c4 = idx & 63;
            const float4* ps = (const float4*)(g_P + (size_t)sd[row] * 256) + c4;
            const float4* pd = (const float4*)(g_P + (size_t)sd[64 + row] * 256) + c4;
            float4 a = *ps, b = *pd;
            float4 r;
            r.x = a.x - b.x; r.y = a.y - b.y; r.z = a.z - b.z; r.w = a.w - b.w;
            *(float4*)(pref + row * LDP + c4 * 4) = r;
        }
        __syncthreads();

        // ---- combine: pre-act = P-diff + EF + b1, relu, write H (tf32) ----
        #pragma unroll
        for (int mt = 0; mt < 2; ++mt)
            #pragma unroll
            for (int c = 0; c < 4; ++c) {
                int r = 32 * mg + 16 * mt + g + 8 * (c >> 1);
                #pragma unroll
                for (int nt = 0; nt < 8; ++nt) {
                    int col = 64 * ng + 8 * nt + 2 * tg + (c & 1);
                    float b1 = (col < 128) ? __ldg(msg_b1 + col) : __ldg(att_b1 + col - 128);
                    float v = pref[r * LDP + col] + acc[mt][nt][c] + b1;
                    pre[r * LDP + col] = f2tf32(fmaxf(v, 0.f));
                }
            }
        __syncthreads();

        // ---- layer-2 mma (K=128, per-branch) ----
        #pragma unroll
        for (int mt = 0; mt < 2; ++mt)
            #pragma unroll
            for (int nt = 0; nt < 8; ++nt)
                #pragma unroll
                for (int c = 0; c < 4; ++c) acc[mt][nt][c] = 0.f;

        #pragma unroll 4
        for (int ks = 0; ks < 16; ++ks) {
            const int kl = 8 * ks;
            unsigned a[2][4];
            #pragma unroll
            for (int mt = 0; mt < 2; ++mt) {
                int row = 32 * mg + 16 * mt + g;
                a[mt][0] = pre[row * LDP + koff + kl + tg];
                a[mt][1] = pre[(row + 8) * LDP + koff + kl + tg];
                a[mt][2] = pre[row * LDP + koff + kl + tg + 4];
                a[mt][3] = pre[(row + 8) * LDP + koff + kl + tg + 4];
            }
            #pragma unroll
            for (int nt = 0; nt < 8; ++nt) {
                int n = 64 * ng + 8 * nt + g;
                unsigned b[2];
                b[0] = w2s[((kl + tg) << 8) + (n ^ (tg << 3))];
                b[1] = w2s[((kl + tg + 4) << 8) + (n ^ (tg << 3))];
                mma_tf32(acc[0][nt], a[0], b);
                mma_tf32(acc[1][nt], a[1], b);
            }
        }
        __syncthreads();   // all layer-2 A-reads done before exchange overwrite

        // ---- exchange: msg raw | att sigmoid ----
        #pragma unroll
        for (int mt = 0; mt < 2; ++mt)
            #pragma unroll
            for (int c = 0; c < 4; ++c) {
                int r = 32 * mg + 16 * mt + g + 8 * (c >> 1);
                #pragma unroll
                for (int nt = 0; nt < 8; ++nt) {
                    int col = 64 * ng + 8 * nt + 2 * tg + (c & 1);
                    float b2 = (col < 128) ? __ldg(msg_b2 + col) : __ldg(att_b2 + col - 128);
                    float v = acc[mt][nt][c] + b2;
                    if (br) v = sigmoidf_fast(v);
                    pref[r * LDP + col] = v;
                }
            }
        __syncthreads();

        // ---- gate + scatter ----
        for (int idx = tid; idx < 64 * 128; idx += ETHREADS) {
            int row = idx >> 7, c = idx & 127;
            int ge = e0 + row;
            if (ge < M_) {
                float v = pref[row * LDP + c] * pref[row * LDP + 128 + c];
                atomicAdd(g_agg + (size_t)sd[64 + row] * 128 + c, v);
            }
        }
        __syncthreads();   // protect pre before next tile
    }
}

// ===================== GRU kernel =====================
extern "C" __global__ void __launch_bounds__(128)
gru_kernel(const float* __restrict__ node_feat,
           const float* __restrict__ w_ih,  // [384][128]
           const float* __restrict__ w_hh,  // [384][128]
           const float* __restrict__ b_ih,
           const float* __restrict__ b_hh,
           float* __restrict__ out, int N_)
{
    __shared__ __align__(16) float agg_s[8 * 128];
    __shared__ __align__(16) float st_s[8 * 128];
    __shared__ float gi_s[8 * 384];
    __shared__ float gh_s[8 * 384];

    const int tid = threadIdx.x;
    const int n0 = blockIdx.x * 8;

    for (int idx = tid; idx < 8 * 128; idx += 128) {
        int n = idx >> 7, c = idx & 127;
        int gn = n0 + n;
        float av = 0.f, sv = 0.f;
        if (gn < N_) {
            av = g_agg[(size_t)gn * 128 + c];
            sv = node_feat[(size_t)gn * 128 + c];
        }
        agg_s[idx] = av;
        st_s[idx]  = sv;
    }
    __syncthreads();

    for (int idx = tid; idx < 8 * 384; idx += 128) {
        int n = idx / 384;
        int j = idx - n * 384;
        const float4* wi4 = (const float4*)(w_ih + j * 128);
        const float4* wh4 = (const float4*)(w_hh + j * 128);
        const float4* x4  = (const float4*)(agg_s + n * 128);
        const float4* s4  = (const float4*)(st_s + n * 128);
        float si = 0.f, sh = 0.f;
        #pragma unroll 8
        for (int k = 0; k < 32; ++k) {
            float4 a = x4[k], b = wi4[k];
            si += a.x * b.x + a.y * b.y + a.z * b.z + a.w * b.w;
            float4 c = s4[k], d = wh4[k];
            sh += c.x * d.x + c.y * d.y + c.z * d.z + c.w * d.w;
        }
        gi_s[idx] = si + b_ih[j];
        gh_s[idx] = sh + b_hh[j];
    }
    __syncthreads();

    for (int idx = tid; idx < 8 * 128; idx += 128) {
        int n = idx >> 7, c = idx & 127;
        int gn = n0 + n;
        if (gn >= N_) continue;
        float ir = gi_s[n * 384 + c];
        float iz = gi_s[n * 384 + 128 + c];
        float in_ = gi_s[n * 384 + 256 + c];
        float hr = gh_s[n * 384 + c];
        float hz = gh_s[n * 384 + 128 + c];
        float hn = gh_s[n * 384 + 256 + c];
        float r = sigmoidf_fast(ir + hr);
        float z = sigmoidf_fast(iz + hz);
        float nv = tanhf(in_ + r * hn);
        out[(size_t)gn * 128 + c] = (1.0f - z) * nv + z * st_s[idx];
    }
}

extern "C" void kernel_launch(void* const* d_in, const int* in_sizes, int n_in,
                              void* d_out, int out_size)
{
    const float* node_feat = (const float*)d_in[0];
    const int*   edge      = (const int*)  d_in[1];
    const float* edge_feat = (const float*)d_in[2];
    const float* node_attr = (const float*)d_in[3];
    const float* edge_attr = (const float*)d_in[4];
    const float* msg_w1    = (const float*)d_in[5];
    const float* msg_b1    = (const float*)d_in[6];
    const float* msg_w2    = (const float*)d_in[7];
    const float* msg_b2    = (const float*)d_in[8];
    const float* att_w1    = (const float*)d_in[9];
    const float* att_b1    = (const float*)d_in[10];
    const float* att_w2    = (const float*)d_in[11];
    const float* att_b2    = (const float*)d_in[12];
    const float* gru_w_ih  = (const float*)d_in[13];
    const float* gru_w_hh  = (const float*)d_in[14];
    const float* gru_b_ih  = (const float*)d_in[15];
    const float* gru_b_hh  = (const float*)d_in[16];
    float* out = (float*)d_out;

    int N_ = in_sizes[0] / DD;
    int M_ = in_sizes[1] / 2;

    cudaFuncSetAttribute(edge_kernel, cudaFuncAttributeMaxDynamicSharedMemorySize,
                         EDGE_SMEM_BYTES);

    size_t tot = (size_t)N_ * DD;
    zero_agg_kernel<<<(int)((tot + 255) / 256), 256>>>();

    int nblocks = (N_ + 63) / 64;
    nodeproj_kernel<<<nblocks, ETHREADS>>>(node_feat, node_attr, edge_attr,
                                           msg_w1, att_w1, N_);

    int ntiles = (M_ + 63) / 64;
    int egrid = ntiles < 148 ? ntiles : 148;
    edge_kernel<<<egrid, ETHREADS, EDGE_SMEM_BYTES>>>(
        edge, edge_feat,
        msg_w1, msg_b1, msg_w2, msg_b2,
        att_w1, att_b1, att_w2, att_b2, M_);

    int gblocks = (N_ + 7) / 8;
    gru_kernel<<<gblocks, 128>>>(node_feat, gru_w_ih, gru_w_hh, gru_b_ih, gru_b_hh, out, N_);
}

// round 9
// speedup vs baseline: 2.0809x; 1.0535x over previous
#include <cuda_runtime.h>
#include <cuda_fp16.h>
#include <cstdint>
#include <math.h>

#define DD 128
#define ETHREADS 256

// Device scratch
__device__ float g_agg[(size_t)50000 * 128];
__device__ float g_P[(size_t)50000 * 256];

__device__ __forceinline__ float sigmoidf_fast(float x) {
    return 1.0f / (1.0f + __expf(-x));
}
__device__ __forceinline__ unsigned f2tf32(float f) {
    unsigned u;
    asm("cvt.rna.tf32.f32 %0, %1;" : "=r"(u) : "f"(f));
    return u;
}
__device__ __forceinline__ void mma_tf32(float c[4], const unsigned a[4], const unsigned b[2]) {
    asm volatile(
        "mma.sync.aligned.m16n8k8.row.col.f32.tf32.tf32.f32 "
        "{%0,%1,%2,%3}, {%4,%5,%6,%7}, {%8,%9}, {%0,%1,%2,%3};"
        : "+f"(c[0]), "+f"(c[1]), "+f"(c[2]), "+f"(c[3])
        : "r"(a[0]), "r"(a[1]), "r"(a[2]), "r"(a[3]), "r"(b[0]), "r"(b[1]));
}
__device__ __forceinline__ void mma_f16(float c[4], const unsigned a[4], const unsigned b[2]) {
    asm volatile(
        "mma.sync.aligned.m16n8k16.row.col.f32.f16.f16.f32 "
        "{%0,%1,%2,%3}, {%4,%5,%6,%7}, {%8,%9}, {%0,%1,%2,%3};"
        : "+f"(c[0]), "+f"(c[1]), "+f"(c[2]), "+f"(c[3])
        : "r"(a[0]), "r"(a[1]), "r"(a[2]), "r"(a[3]), "r"(b[0]), "r"(b[1]));
}
__device__ __forceinline__ uint32_t pack_h2(float lo, float hi) {
    __half2 h = __floats2half2_rn(lo, hi);
    return *(uint32_t*)&h;
}

__global__ void zero_agg_kernel() {
    size_t i = (size_t)blockIdx.x * blockDim.x + threadIdx.x;
    if (i < (size_t)50000 * 128) g_agg[i] = 0.0f;
}

// ===================== Node projection kernel (tf32) =====================
#define NLDA 36
#define NLDW 264
extern "C" __global__ void __launch_bounds__(ETHREADS)
nodeproj_kernel(const float* __restrict__ node_feat,
                const float* __restrict__ node_attr,   // [2][N]
                const float* __restrict__ edge_attr,   // [N][128]
                const float* __restrict__ msg_w1,
                const float* __restrict__ att_w1,
                int N_)
{
    __shared__ uint32_t xs[64 * NLDA];
    __shared__ uint32_t ws[32 * NLDW];
    __shared__ float wna[2][256];

    const int tid  = threadIdx.x;
    const int lane = tid & 31;
    const int wid  = tid >> 5;
    const int g    = lane >> 2;
    const int tg   = lane & 3;
    const int mg   = wid >> 2;
    const int ng   = wid & 3;
    const int n0   = blockIdx.x * 64;

    for (int c = tid; c < 256; c += ETHREADS) {
        const float* w1 = (c < 128) ? msg_w1 : att_w1;
        int cc = c & 127;
        wna[0][c] = w1[288 * 128 + cc];
        wna[1][c] = w1[289 * 128 + cc];
    }

    float acc[2][8][4];
    #pragma unroll
    for (int mt = 0; mt < 2; ++mt)
        #pragma unroll
        for (int nt = 0; nt < 8; ++nt)
            #pragma unroll
            for (int c = 0; c < 4; ++c) acc[mt][nt][c] = 0.f;

    for (int s = 0; s < 8; ++s) {
        const int k0 = 32 * s;
        for (int idx = tid; idx < 64 * 32; idx += ETHREADS) {
            int row = idx >> 5, kk = idx & 31;
            int n = n0 + row;
            float v = 0.f;
            if (n < N_) {
                int k = k0 + kk;
                v = (k < 128) ? node_feat[(size_t)n * 128 + k]
                              : edge_attr[(size_t)n * 128 + (k - 128)];
            }
            xs[row * NLDA + kk] = f2tf32(v);
        }
        for (int idx = tid; idx < 32 * 256; idx += ETHREADS) {
            int kk = idx >> 8, c = idx & 255;
            int k = k0 + kk;
            int wrow = (k < 128) ? k : (k + 32);
            float v = (c < 128) ? msg_w1[wrow * 128 + c] : att_w1[wrow * 128 + (c - 128)];
            ws[kk * NLDW + c] = f2tf32(v);
        }
        __syncthreads();
        #pragma unroll
        for (int ks = 0; ks < 4; ++ks) {
            const int kl = 8 * ks;
            unsigned a[2][4];
            #pragma unroll
            for (int mt = 0; mt < 2; ++mt) {
                int row = 32 * mg + 16 * mt + g;
                a[mt][0] = xs[row * NLDA + kl + tg];
                a[mt][1] = xs[(row + 8) * NLDA + kl + tg];
                a[mt][2] = xs[row * NLDA + kl + tg + 4];
                a[mt][3] = xs[(row + 8) * NLDA + kl + tg + 4];
            }
            #pragma unroll
            for (int nt = 0; nt < 8; ++nt) {
                int cb = 64 * ng + 8 * nt + g;
                unsigned b[2];
                b[0] = ws[(kl + tg) * NLDW + cb];
                b[1] = ws[(kl + tg + 4) * NLDW + cb];
                mma_tf32(acc[0][nt], a[0], b);
                mma_tf32(acc[1][nt], a[1], b);
            }
        }
        __syncthreads();
    }

    #pragma unroll
    for (int mt = 0; mt < 2; ++mt)
        #pragma unroll
        for (int c = 0; c < 4; ++c) {
            int r = 32 * mg + 16 * mt + g + 8 * (c >> 1);
            int n = n0 + r;
            if (n >= N_) continue;
            float na0 = node_attr[n];
            float na1 = node_attr[N_ + n];
            #pragma unroll
            for (int nt = 0; nt < 8; ++nt) {
                int col = 64 * ng + 8 * nt + 2 * tg + (c & 1);
                g_P[(size_t)n * 256 + col] =
                    acc[mt][nt][c] + na0 * wna[0][col] + na1 * wna[1][col];
            }
        }
}

// ===================== Edge kernel (persistent, fp16 MMA) =====================
// Byte offsets into dynamic smem:
//   w2s  [256 n][136 halves]  fp16   69632 B   (n-major, +8 halves pad)
//   wefs [256 n][40 halves]   fp16   20480 B
//   xs   [64 r][40 halves]    fp16    5120 B   (EF tile)
//   hbuf [64 r][264 halves]   fp16   33792 B   (relu layer-1 out, msg|att)
//   pre  [64 r][260 f32]      f32    66560 B   (P-diff gather / exchange)
//   sd   128 int                       512 B
//   b1s,b2s 256 f32 each              2048 B
#define W2_OFF   0
#define WEF_OFF  69632
#define XS_OFF   90112
#define H_OFF    95232
#define PRE_OFF  129024
#define SD_OFF   195584
#define B1_OFF   196096
#define B2_OFF   197120
#define EDGE_SMEM_BYTES 198144
#define LDW2W 68    // w2s stride in 32-bit words
#define LDWEFW 20
#define LDXSW 20
#define LDHW 132
#define LDP 260

extern "C" __global__ void __launch_bounds__(ETHREADS, 1)
edge_kernel(const int*   __restrict__ edge,
            const float* __restrict__ edge_feat,
            const float* __restrict__ msg_w1, const float* __restrict__ msg_b1,
            const float* __restrict__ msg_w2, const float* __restrict__ msg_b2,
            const float* __restrict__ att_w1, const float* __restrict__ att_b1,
            const float* __restrict__ att_w2, const float* __restrict__ att_b2,
            int M_)
{
    extern __shared__ char smraw[];
    uint32_t* w232  = (uint32_t*)(smraw + W2_OFF);
    uint32_t* wef32 = (uint32_t*)(smraw + WEF_OFF);
    uint32_t* xs32  = (uint32_t*)(smraw + XS_OFF);
    uint32_t* h32   = (uint32_t*)(smraw + H_OFF);
    float*    pref  = (float*)(smraw + PRE_OFF);
    int*      sd    = (int*)(smraw + SD_OFF);
    float*    b1s   = (float*)(smraw + B1_OFF);
    float*    b2s   = (float*)(smraw + B2_OFF);
    __half*   w2h   = (__half*)(smraw + W2_OFF);
    __half*   wefh  = (__half*)(smraw + WEF_OFF);

    const int tid  = threadIdx.x;
    const int lane = tid & 31;
    const int wid  = tid >> 5;
    const int g    = lane >> 2;
    const int tg   = lane & 3;
    const int mg   = wid >> 2;        // row group: rows 32*mg
    const int ng   = wid & 3;         // col group: cols 64*ng
    const int br   = ng >> 1;         // 0=msg, 1=att
    const int koffw = br * 64;        // branch k offset in h (words)

    // ---- one-time weight/bias staging (n-major fp16) ----
    for (int idx = tid; idx < 256 * 128; idx += ETHREADS) {
        int n = idx >> 7, k = idx & 127;
        float v = (n < 128) ? msg_w2[k * 128 + n] : att_w2[k * 128 + (n - 128)];
        w2h[n * 136 + k] = __float2half_rn(v);
    }
    for (int idx = tid; idx < 256 * 32; idx += ETHREADS) {
        int n = idx >> 5, k = idx & 31;
        float v = (n < 128) ? msg_w1[(128 + k) * 128 + n] : att_w1[(128 + k) * 128 + (n - 128)];
        wefh[n * 40 + k] = __float2half_rn(v);
    }
    for (int c = tid; c < 256; c += ETHREADS) {
        b1s[c] = (c < 128) ? msg_b1[c] : att_b1[c - 128];
        b2s[c] = (c < 128) ? msg_b2[c] : att_b2[c - 128];
    }
    __syncthreads();

    const int ntiles = (M_ + 63) >> 6;
    for (int t = blockIdx.x; t < ntiles; t += gridDim.x) {
        const int e0 = t << 6;

        // ---- Phase A: endpoints + EF -> xs (fp16) ----
        if (tid < 64) {
            int ge = e0 + tid;
            int s = 0, d = 0;
            if (ge < M_) { s = edge[2 * ge]; d = edge[2 * ge + 1]; }
            sd[tid] = s;
            sd[64 + tid] = d;
        }
        for (int idx = tid; idx < 64 * 16; idx += ETHREADS) {
            int row = idx >> 4, w = idx & 15;
            int ge = e0 + row;
            float v0 = 0.f, v1 = 0.f;
            if (ge < M_) {
                v0 = edge_feat[(size_t)ge * 32 + 2 * w];
                v1 = edge_feat[(size_t)ge * 32 + 2 * w + 1];
            }
            xs32[row * LDXSW + w] = pack_h2(v0, v1);
        }
        __syncthreads();

        // ---- Phase B: EF mma (reads xs) + P-diff gather (writes pre) ----
        float acc[2][8][4];
        #pragma unroll
        for (int mt = 0; mt < 2; ++mt)
            #pragma unroll
            for (int nt = 0; nt < 8; ++nt)
                #pragma unroll
                for (int c = 0; c < 4; ++c) acc[mt][nt][c] = 0.f;

        #pragma unroll
        for (int ks = 0; ks < 2; ++ks) {
            const int k0w = ks * 8;
            unsigned a[2][4];
            #pragma unroll
            for (int mt = 0; mt < 2; ++mt) {
                int row = 32 * mg + 16 * mt + g;
                a[mt][0] = xs32[row * LDXSW + k0w + tg];
                a[mt][1] = xs32[(row + 8) * LDXSW + k0w + tg];
                a[mt][2] = xs32[row * LDXSW + k0w + tg + 4];
                a[mt][3] = xs32[(row + 8) * LDXSW + k0w + tg + 4];
            }
            #pragma unroll
            for (int nt = 0; nt < 8; ++nt) {
                int n = 64 * ng + 8 * nt + g;
                unsigned b[2];
                b[0] = wef32[n * LDWEFW + k0w + tg];
                b[1] = wef32[n * LDWEFW + k0w + tg + 4];
                mma_f16(acc[0][nt], a[0], b);
                mma_f16(acc[1][nt], a[1], b);
            }
        }

        for (int idx = tid; idx < 64 * 64; idx += ETHREADS) {
            int row = idx >> 6, c4 = idx & 63;
            const float4* ps = (const float4*)(g_P + (size_t)sd[row] * 256) + c4;
            const float4* pd = (const float4*)(g_P + (size_t)sd[64 + row] * 256) + c4;
            float4 a = *ps, b = *pd;
            float4 r;
            r.x = a.x - b.x; r.y = a.y - b.y; r.z = a.z - b.z; r.w = a.w - b.w;
            *(float4*)(pref + row * LDP + c4 * 4) = r;
        }
        __syncthreads();

        // ---- Phase C: combine -> relu -> h (fp16) ----
        #pragma unroll
        for (int mt = 0; mt < 2; ++mt)
            #pragma unroll
            for (int c2 = 0; c2 < 2; ++c2) {
                int r = 32 * mg + 16 * mt + g + 8 * c2;
                #pragma unroll
                for (int nt = 0; nt < 8; ++nt) {
                    int colb = 64 * ng + 8 * nt + 2 * tg;
                    float v0 = pref[r * LDP + colb]     + acc[mt][nt][2 * c2]     + b1s[colb];
                    float v1 = pref[r * LDP + colb + 1] + acc[mt][nt][2 * c2 + 1] + b1s[colb + 1];
                    h32[r * LDHW + (colb >> 1)] = pack_h2(fmaxf(v0, 0.f), fmaxf(v1, 0.f));
                }
            }
        __syncthreads();

        // ---- Phase D: layer-2 mma (reads h, w2s) + exchange write (pre) ----
        #pragma unroll
        for (int mt = 0; mt < 2; ++mt)
            #pragma unroll
            for (int nt = 0; nt < 8; ++nt)
                #pragma unroll
                for (int c = 0; c < 4; ++c) acc[mt][nt][c] = 0.f;

        #pragma unroll
        for (int ks = 0; ks < 8; ++ks) {
            const int k0w = ks * 8;
            unsigned a[2][4];
            #pragma unroll
            for (int mt = 0; mt < 2; ++mt) {
                int row = 32 * mg + 16 * mt + g;
                a[mt][0] = h32[row * LDHW + koffw + k0w + tg];
                a[mt][1] = h32[(row + 8) * LDHW + koffw + k0w + tg];
                a[mt][2] = h32[row * LDHW + koffw + k0w + tg + 4];
                a[mt][3] = h32[(row + 8) * LDHW + koffw + k0w + tg + 4];
            }
            #pragma unroll
            for (int nt = 0; nt < 8; ++nt) {
                int n = 64 * ng + 8 * nt + g;
                unsigned b[2];
                b[0] = w232[n * LDW2W + k0w + tg];
                b[1] = w232[n * LDW2W + k0w + tg + 4];
                mma_f16(acc[0][nt], a[0], b);
                mma_f16(acc[1][nt], a[1], b);
            }
        }

        #pragma unroll
        for (int mt = 0; mt < 2; ++mt)
            #pragma unroll
            for (int c = 0; c < 4; ++c) {
                int r = 32 * mg + 16 * mt + g + 8 * (c >> 1);
                #pragma unroll
                for (int nt = 0; nt < 8; ++nt) {
                    int col = 64 * ng + 8 * nt + 2 * tg + (c & 1);
                    float v = acc[mt][nt][c] + b2s[col];
                    if (br) v = sigmoidf_fast(v);
                    pref[r * LDP + col] = v;
                }
            }
        __syncthreads();

        // ---- Phase E: gate + scatter ----
        for (int idx = tid; idx < 64 * 128; idx += ETHREADS) {
            int row = idx >> 7, c = idx & 127;
            int ge = e0 + row;
            if (ge < M_) {
                float v = pref[row * LDP + c] * pref[row * LDP + 128 + c];
                atomicAdd(g_agg + (size_t)sd[64 + row] * 128 + c, v);
            }
        }
        __syncthreads();
    }
}

// ===================== GRU kernel =====================
extern "C" __global__ void __launch_bounds__(128)
gru_kernel(const float* __restrict__ node_feat,
           const float* __restrict__ w_ih,  // [384][128]
           const float* __restrict__ w_hh,  // [384][128]
           const float* __restrict__ b_ih,
           const float* __restrict__ b_hh,
           float* __restrict__ out, int N_)
{
    __shared__ __align__(16) float agg_s[8 * 128];
    __shared__ __align__(16) float st_s[8 * 128];
    __shared__ float gi_s[8 * 384];
    __shared__ float gh_s[8 * 384];

    const int tid = threadIdx.x;
    const int n0 = blockIdx.x * 8;

    for (int idx = tid; idx < 8 * 128; idx += 128) {
        int n = idx >> 7, c = idx & 127;
        int gn = n0 + n;
        float av = 0.f, sv = 0.f;
        if (gn < N_) {
            av = g_agg[(size_t)gn * 128 + c];
            sv = node_feat[(size_t)gn * 128 + c];
        }
        agg_s[idx] = av;
        st_s[idx]  = sv;
    }
    __syncthreads();

    for (int idx = tid; idx < 8 * 384; idx += 128) {
        int n = idx / 384;
        int j = idx - n * 384;
        const float4* wi4 = (const float4*)(w_ih + j * 128);
        const float4* wh4 = (const float4*)(w_hh + j * 128);
        const float4* x4  = (const float4*)(agg_s + n * 128);
        const float4* s4  = (const float4*)(st_s + n * 128);
        float si = 0.f, sh = 0.f;
        #pragma unroll 8
        for (int k = 0; k < 32; ++k) {
            float4 a = x4[k], b = wi4[k];
            si += a.x * b.x + a.y * b.y + a.z * b.z + a.w * b.w;
            float4 c = s4[k], d = wh4[k];
            sh += c.x * d.x + c.y * d.y + c.z * d.z + c.w * d.w;
        }
        gi_s[idx] = si + b_ih[j];
        gh_s[idx] = sh + b_hh[j];
    }
    __syncthreads();

    for (int idx = tid; idx < 8 * 128; idx += 128) {
        int n = idx >> 7, c = idx & 127;
        int gn = n0 + n;
        if (gn >= N_) continue;
        float ir = gi_s[n * 384 + c];
        float iz = gi_s[n * 384 + 128 + c];
        float in_ = gi_s[n * 384 + 256 + c];
        float hr = gh_s[n * 384 + c];
        float hz = gh_s[n * 384 + 128 + c];
        float hn = gh_s[n * 384 + 256 + c];
        float r = sigmoidf_fast(ir + hr);
        float z = sigmoidf_fast(iz + hz);
        float nv = tanhf(in_ + r * hn);
        out[(size_t)gn * 128 + c] = (1.0f - z) * nv + z * st_s[idx];
    }
}

extern "C" void kernel_launch(void* const* d_in, const int* in_sizes, int n_in,
                              void* d_out, int out_size)
{
    const float* node_feat = (const float*)d_in[0];
    const int*   edge      = (const int*)  d_in[1];
    const float* edge_feat = (const float*)d_in[2];
    const float* node_attr = (const float*)d_in[3];
    const float* edge_attr = (const float*)d_in[4];
    const float* msg_w1    = (const float*)d_in[5];
    const float* msg_b1    = (const float*)d_in[6];
    const float* msg_w2    = (const float*)d_in[7];
    const float* msg_b2    = (const float*)d_in[8];
    const float* att_w1    = (const float*)d_in[9];
    const float* att_b1    = (const float*)d_in[10];
    const float* att_w2    = (const float*)d_in[11];
    const float* att_b2    = (const float*)d_in[12];
    const float* gru_w_ih  = (const float*)d_in[13];
    const float* gru_w_hh  = (const float*)d_in[14];
    const float* gru_b_ih  = (const float*)d_in[15];
    const float* gru_b_hh  = (const float*)d_in[16];
    float* out = (float*)d_out;

    int N_ = in_sizes[0] / DD;
    int M_ = in_sizes[1] / 2;

    cudaFuncSetAttribute(edge_kernel, cudaFuncAttributeMaxDynamicSharedMemorySize,
                         EDGE_SMEM_BYTES);

    size_t tot = (size_t)N_ * DD;
    zero_agg_kernel<<<(int)((tot + 255) / 256), 256>>>();

    int nblocks = (N_ + 63) / 64;
    nodeproj_kernel<<<nblocks, ETHREADS>>>(node_feat, node_attr, edge_attr,
                                           msg_w1, att_w1, N_);

    int ntiles = (M_ + 63) / 64;
    int egrid = ntiles < 148 ? ntiles : 148;
    edge_kernel<<<egrid, ETHREADS, EDGE_SMEM_BYTES>>>(
        edge, edge_feat,
        msg_w1, msg_b1, msg_w2, msg_b2,
        att_w1, att_b1, att_w2, att_b2, M_);

    int gblocks = (N_ + 7) / 8;
    gru_kernel<<<gblocks, 128>>>(node_feat, gru_w_ih, gru_w_hh, gru_b_ih, gru_b_hh, out, N_);
}

// round 10
// speedup vs baseline: 2.2405x; 1.0767x over previous
#include <cuda_runtime.h>
#include <cuda_fp16.h>
#include <cstdint>
#include <math.h>

#define DD 128
#define NTHREADS 256
#define ETH 512

// Device scratch
__device__ float g_agg[(size_t)50000 * 128];
__device__ float g_P[(size_t)50000 * 256];

__device__ __forceinline__ float sigmoidf_fast(float x) {
    return 1.0f / (1.0f + __expf(-x));
}
__device__ __forceinline__ unsigned f2tf32(float f) {
    unsigned u;
    asm("cvt.rna.tf32.f32 %0, %1;" : "=r"(u) : "f"(f));
    return u;
}
__device__ __forceinline__ void mma_tf32(float c[4], const unsigned a[4], const unsigned b[2]) {
    asm volatile(
        "mma.sync.aligned.m16n8k8.row.col.f32.tf32.tf32.f32 "
        "{%0,%1,%2,%3}, {%4,%5,%6,%7}, {%8,%9}, {%0,%1,%2,%3};"
        : "+f"(c[0]), "+f"(c[1]), "+f"(c[2]), "+f"(c[3])
        : "r"(a[0]), "r"(a[1]), "r"(a[2]), "r"(a[3]), "r"(b[0]), "r"(b[1]));
}
__device__ __forceinline__ void mma_f16(float c[4], const unsigned a[4], const unsigned b[2]) {
    asm volatile(
        "mma.sync.aligned.m16n8k16.row.col.f32.f16.f16.f32 "
        "{%0,%1,%2,%3}, {%4,%5,%6,%7}, {%8,%9}, {%0,%1,%2,%3};"
        : "+f"(c[0]), "+f"(c[1]), "+f"(c[2]), "+f"(c[3])
        : "r"(a[0]), "r"(a[1]), "r"(a[2]), "r"(a[3]), "r"(b[0]), "r"(b[1]));
}
__device__ __forceinline__ uint32_t pack_h2(float lo, float hi) {
    __half2 h = __floats2half2_rn(lo, hi);
    return *(uint32_t*)&h;
}

__global__ void zero_agg_kernel() {
    size_t i = (size_t)blockIdx.x * blockDim.x + threadIdx.x;
    if (i < (size_t)50000 * 128) g_agg[i] = 0.0f;
}

// ===================== Node projection kernel (tf32) =====================
#define NLDA 36
#define NLDW 264
extern "C" __global__ void __launch_bounds__(NTHREADS)
nodeproj_kernel(const float* __restrict__ node_feat,
                const float* __restrict__ node_attr,   // [2][N]
                const float* __restrict__ edge_attr,   // [N][128]
                const float* __restrict__ msg_w1,
                const float* __restrict__ att_w1,
                int N_)
{
    __shared__ uint32_t xs[64 * NLDA];
    __shared__ uint32_t ws[32 * NLDW];
    __shared__ float wna[2][256];

    const int tid  = threadIdx.x;
    const int lane = tid & 31;
    const int wid  = tid >> 5;
    const int g    = lane >> 2;
    const int tg   = lane & 3;
    const int mg   = wid >> 2;
    const int ng   = wid & 3;
    const int n0   = blockIdx.x * 64;

    for (int c = tid; c < 256; c += NTHREADS) {
        const float* w1 = (c < 128) ? msg_w1 : att_w1;
        int cc = c & 127;
        wna[0][c] = w1[288 * 128 + cc];
        wna[1][c] = w1[289 * 128 + cc];
    }

    float acc[2][8][4];
    #pragma unroll
    for (int mt = 0; mt < 2; ++mt)
        #pragma unroll
        for (int nt = 0; nt < 8; ++nt)
            #pragma unroll
            for (int c = 0; c < 4; ++c) acc[mt][nt][c] = 0.f;

    for (int s = 0; s < 8; ++s) {
        const int k0 = 32 * s;
        for (int idx = tid; idx < 64 * 32; idx += NTHREADS) {
            int row = idx >> 5, kk = idx & 31;
            int n = n0 + row;
            float v = 0.f;
            if (n < N_) {
                int k = k0 + kk;
                v = (k < 128) ? node_feat[(size_t)n * 128 + k]
                              : edge_attr[(size_t)n * 128 + (k - 128)];
            }
            xs[row * NLDA + kk] = f2tf32(v);
        }
        for (int idx = tid; idx < 32 * 256; idx += NTHREADS) {
            int kk = idx >> 8, c = idx & 255;
            int k = k0 + kk;
            int wrow = (k < 128) ? k : (k + 32);
            float v = (c < 128) ? msg_w1[wrow * 128 + c] : att_w1[wrow * 128 + (c - 128)];
            ws[kk * NLDW + c] = f2tf32(v);
        }
        __syncthreads();
        #pragma unroll
        for (int ks = 0; ks < 4; ++ks) {
            const int kl = 8 * ks;
            unsigned a[2][4];
            #pragma unroll
            for (int mt = 0; mt < 2; ++mt) {
                int row = 32 * mg + 16 * mt + g;
                a[mt][0] = xs[row * NLDA + kl + tg];
                a[mt][1] = xs[(row + 8) * NLDA + kl + tg];
                a[mt][2] = xs[row * NLDA + kl + tg + 4];
                a[mt][3] = xs[(row + 8) * NLDA + kl + tg + 4];
            }
            #pragma unroll
            for (int nt = 0; nt < 8; ++nt) {
                int cb = 64 * ng + 8 * nt + g;
                unsigned b[2];
                b[0] = ws[(kl + tg) * NLDW + cb];
                b[1] = ws[(kl + tg + 4) * NLDW + cb];
                mma_tf32(acc[0][nt], a[0], b);
                mma_tf32(acc[1][nt], a[1], b);
            }
        }
        __syncthreads();
    }

    #pragma unroll
    for (int mt = 0; mt < 2; ++mt)
        #pragma unroll
        for (int c = 0; c < 4; ++c) {
            int r = 32 * mg + 16 * mt + g + 8 * (c >> 1);
            int n = n0 + r;
            if (n >= N_) continue;
            float na0 = node_attr[n];
            float na1 = node_attr[N_ + n];
            #pragma unroll
            for (int nt = 0; nt < 8; ++nt) {
                int col = 64 * ng + 8 * nt + 2 * tg + (c & 1);
                g_P[(size_t)n * 256 + col] =
                    acc[mt][nt][c] + na0 * wna[0][col] + na1 * wna[1][col];
            }
        }
}

// ===================== Edge kernel (persistent, fp16 MMA, 512 thr) =====================
// Byte offsets into dynamic smem (same as R9):
#define W2_OFF   0
#define WEF_OFF  69632
#define XS_OFF   90112
#define H_OFF    95232
#define PRE_OFF  129024
#define SD_OFF   195584
#define B1_OFF   196096
#define B2_OFF   197120
#define EDGE_SMEM_BYTES 198144
#define LDW2W 68    // w2s stride in 32-bit words
#define LDWEFW 20
#define LDXSW 20
#define LDHW 132
#define LDP 260

extern "C" __global__ void __launch_bounds__(ETH, 1)
edge_kernel(const int*   __restrict__ edge,
            const float* __restrict__ edge_feat,
            const float* __restrict__ msg_w1, const float* __restrict__ msg_b1,
            const float* __restrict__ msg_w2, const float* __restrict__ msg_b2,
            const float* __restrict__ att_w1, const float* __restrict__ att_b1,
            const float* __restrict__ att_w2, const float* __restrict__ att_b2,
            int M_, int t0, int t1)
{
    extern __shared__ char smraw[];
    uint32_t* w232  = (uint32_t*)(smraw + W2_OFF);
    uint32_t* wef32 = (uint32_t*)(smraw + WEF_OFF);
    uint32_t* xs32  = (uint32_t*)(smraw + XS_OFF);
    uint32_t* h32   = (uint32_t*)(smraw + H_OFF);
    float*    pref  = (float*)(smraw + PRE_OFF);
    int*      sd    = (int*)(smraw + SD_OFF);
    float*    b1s   = (float*)(smraw + B1_OFF);
    float*    b2s   = (float*)(smraw + B2_OFF);
    __half*   w2h   = (__half*)(smraw + W2_OFF);
    __half*   wefh  = (__half*)(smraw + WEF_OFF);

    const int tid  = threadIdx.x;
    const int lane = tid & 31;
    const int wid  = tid >> 5;          // 0..15
    const int g    = lane >> 2;
    const int tg   = lane & 3;
    const int mg   = wid & 3;           // row group: rows 16*mg
    const int ng   = wid >> 2;          // col group: cols 64*ng (SMSP-balanced branches)
    const int br   = ng >> 1;           // 0=msg, 1=att
    const int koffw = br * 64;          // branch k offset in h (words)
    const int r0   = 16 * mg;
    const int c0   = 64 * ng;

    // ---- one-time weight/bias staging (n-major fp16) ----
    for (int idx = tid; idx < 256 * 128; idx += ETH) {
        int n = idx >> 7, k = idx & 127;
        float v = (n < 128) ? msg_w2[k * 128 + n] : att_w2[k * 128 + (n - 128)];
        w2h[n * 136 + k] = __float2half_rn(v);
    }
    for (int idx = tid; idx < 256 * 32; idx += ETH) {
        int n = idx >> 5, k = idx & 31;
        float v = (n < 128) ? msg_w1[(128 + k) * 128 + n] : att_w1[(128 + k) * 128 + (n - 128)];
        wefh[n * 40 + k] = __float2half_rn(v);
    }
    for (int c = tid; c < 256; c += ETH) {
        b1s[c] = (c < 128) ? msg_b1[c] : att_b1[c - 128];
        b2s[c] = (c < 128) ? msg_b2[c] : att_b2[c - 128];
    }
    __syncthreads();

    for (int t = t0 + blockIdx.x; t < t1; t += gridDim.x) {
        const int e0 = t << 6;

        // ---- Phase A: endpoints + EF -> xs (fp16) ----
        if (tid < 64) {
            int ge = e0 + tid;
            int s = 0, d = 0;
            if (ge < M_) { s = edge[2 * ge]; d = edge[2 * ge + 1]; }
            sd[tid] = s;
            sd[64 + tid] = d;
        }
        for (int idx = tid; idx < 64 * 16; idx += ETH) {
            int row = idx >> 4, w = idx & 15;
            int ge = e0 + row;
            float v0 = 0.f, v1 = 0.f;
            if (ge < M_) {
                v0 = edge_feat[(size_t)ge * 32 + 2 * w];
                v1 = edge_feat[(size_t)ge * 32 + 2 * w + 1];
            }
            xs32[row * LDXSW + w] = pack_h2(v0, v1);
        }
        __syncthreads();

        // ---- Phase B: P-diff gather (LDGs first) + EF mma ----
        for (int idx = tid; idx < 64 * 64; idx += ETH) {
            int row = idx >> 6, c4 = idx & 63;
            const float4* ps = (const float4*)(g_P + (size_t)sd[row] * 256) + c4;
            const float4* pd = (const float4*)(g_P + (size_t)sd[64 + row] * 256) + c4;
            float4 a = *ps, b = *pd;
            float4 r;
            r.x = a.x - b.x; r.y = a.y - b.y; r.z = a.z - b.z; r.w = a.w - b.w;
            *(float4*)(pref + row * LDP + c4 * 4) = r;
        }

        float acc[8][4];
        #pragma unroll
        for (int nt = 0; nt < 8; ++nt)
            #pragma unroll
            for (int c = 0; c < 4; ++c) acc[nt][c] = 0.f;

        #pragma unroll
        for (int ks = 0; ks < 2; ++ks) {
            const int k0w = ks * 8;
            unsigned a[4];
            a[0] = xs32[(r0 + g) * LDXSW + k0w + tg];
            a[1] = xs32[(r0 + g + 8) * LDXSW + k0w + tg];
            a[2] = xs32[(r0 + g) * LDXSW + k0w + tg + 4];
            a[3] = xs32[(r0 + g + 8) * LDXSW + k0w + tg + 4];
            #pragma unroll
            for (int nt = 0; nt < 8; ++nt) {
                int n = c0 + 8 * nt + g;
                unsigned b[2];
                b[0] = wef32[n * LDWEFW + k0w + tg];
                b[1] = wef32[n * LDWEFW + k0w + tg + 4];
                mma_f16(acc[nt], a, b);
            }
        }
        __syncthreads();

        // ---- Phase C: combine -> relu -> h (fp16) ----
        #pragma unroll
        for (int c2 = 0; c2 < 2; ++c2) {
            int r = r0 + g + 8 * c2;
            #pragma unroll
            for (int nt = 0; nt < 8; ++nt) {
                int colb = c0 + 8 * nt + 2 * tg;
                float v0 = pref[r * LDP + colb]     + acc[nt][2 * c2]     + b1s[colb];
                float v1 = pref[r * LDP + colb + 1] + acc[nt][2 * c2 + 1] + b1s[colb + 1];
                h32[r * LDHW + (colb >> 1)] = pack_h2(fmaxf(v0, 0.f), fmaxf(v1, 0.f));
            }
        }
        __syncthreads();

        // ---- Phase D: layer-2 mma ----
        #pragma unroll
        for (int nt = 0; nt < 8; ++nt)
            #pragma unroll
            for (int c = 0; c < 4; ++c) acc[nt][c] = 0.f;

        #pragma unroll
        for (int ks = 0; ks < 8; ++ks) {
            const int k0w = ks * 8;
            unsigned a[4];
            a[0] = h32[(r0 + g) * LDHW + koffw + k0w + tg];
            a[1] = h32[(r0 + g + 8) * LDHW + koffw + k0w + tg];
            a[2] = h32[(r0 + g) * LDHW + koffw + k0w + tg + 4];
            a[3] = h32[(r0 + g + 8) * LDHW + koffw + k0w + tg + 4];
            #pragma unroll
            for (int nt = 0; nt < 8; ++nt) {
                int n = c0 + 8 * nt + g;
                unsigned b[2];
                b[0] = w232[n * LDW2W + k0w + tg];
                b[1] = w232[n * LDW2W + k0w + tg + 4];
                mma_f16(acc[nt], a, b);
            }
        }

        #pragma unroll
        for (int c = 0; c < 4; ++c) {
            int r = r0 + g + 8 * (c >> 1);
            #pragma unroll
            for (int nt = 0; nt < 8; ++nt) {
                int col = c0 + 8 * nt + 2 * tg + (c & 1);
                float v = acc[nt][c] + b2s[col];
                if (br) v = sigmoidf_fast(v);
                pref[r * LDP + col] = v;
            }
        }
        __syncthreads();

        // ---- Phase E: gate + scatter ----
        for (int idx = tid; idx < 64 * 128; idx += ETH) {
            int row = idx >> 7, c = idx & 127;
            int ge = e0 + row;
            if (ge < M_) {
                float v = pref[row * LDP + c] * pref[row * LDP + 128 + c];
                atomicAdd(g_agg + (size_t)sd[64 + row] * 128 + c, v);
            }
        }
        __syncthreads();
    }
}

// ===================== GRU kernel =====================
extern "C" __global__ void __launch_bounds__(128)
gru_kernel(const float* __restrict__ node_feat,
           const float* __restrict__ w_ih,  // [384][128]
           const float* __restrict__ w_hh,  // [384][128]
           const float* __restrict__ b_ih,
           const float* __restrict__ b_hh,
           float* __restrict__ out, int N_)
{
    __shared__ __align__(16) float agg_s[8 * 128];
    __shared__ __align__(16) float st_s[8 * 128];
    __shared__ float gi_s[8 * 384];
    __shared__ float gh_s[8 * 384];

    const int tid = threadIdx.x;
    const int n0 = blockIdx.x * 8;

    for (int idx = tid; idx < 8 * 128; idx += 128) {
        int n = idx >> 7, c = idx & 127;
        int gn = n0 + n;
        float av = 0.f, sv = 0.f;
        if (gn < N_) {
            av = g_agg[(size_t)gn * 128 + c];
            sv = node_feat[(size_t)gn * 128 + c];
        }
        agg_s[idx] = av;
        st_s[idx]  = sv;
    }
    __syncthreads();

    for (int idx = tid; idx < 8 * 384; idx += 128) {
        int n = idx / 384;
        int j = idx - n * 384;
        const float4* wi4 = (const float4*)(w_ih + j * 128);
        const float4* wh4 = (const float4*)(w_hh + j * 128);
        const float4* x4  = (const float4*)(agg_s + n * 128);
        const float4* s4  = (const float4*)(st_s + n * 128);
        float si = 0.f, sh = 0.f;
        #pragma unroll 8
        for (int k = 0; k < 32; ++k) {
            float4 a = x4[k], b = wi4[k];
            si += a.x * b.x + a.y * b.y + a.z * b.z + a.w * b.w;
            float4 c = s4[k], d = wh4[k];
            sh += c.x * d.x + c.y * d.y + c.z * d.z + c.w * d.w;
        }
        gi_s[idx] = si + b_ih[j];
        gh_s[idx] = sh + b_hh[j];
    }
    __syncthreads();

    for (int idx = tid; idx < 8 * 128; idx += 128) {
        int n = idx >> 7, c = idx & 127;
        int gn = n0 + n;
        if (gn >= N_) continue;
        float ir = gi_s[n * 384 + c];
        float iz = gi_s[n * 384 + 128 + c];
        float in_ = gi_s[n * 384 + 256 + c];
        float hr = gh_s[n * 384 + c];
        float hz = gh_s[n * 384 + 128 + c];
        float hn = gh_s[n * 384 + 256 + c];
        float r = sigmoidf_fast(ir + hr);
        float z = sigmoidf_fast(iz + hz);
        float nv = tanhf(in_ + r * hn);
        out[(size_t)gn * 128 + c] = (1.0f - z) * nv + z * st_s[idx];
    }
}

extern "C" void kernel_launch(void* const* d_in, const int* in_sizes, int n_in,
                              void* d_out, int out_size)
{
    const float* node_feat = (const float*)d_in[0];
    const int*   edge      = (const int*)  d_in[1];
    const float* edge_feat = (const float*)d_in[2];
    const float* node_attr = (const float*)d_in[3];
    const float* edge_attr = (const float*)d_in[4];
    const float* msg_w1    = (const float*)d_in[5];
    const float* msg_b1    = (const float*)d_in[6];
    const float* msg_w2    = (const float*)d_in[7];
    const float* msg_b2    = (const float*)d_in[8];
    const float* att_w1    = (const float*)d_in[9];
    const float* att_b1    = (const float*)d_in[10];
    const float* att_w2    = (const float*)d_in[11];
    const float* att_b2    = (const float*)d_in[12];
    const float* gru_w_ih  = (const float*)d_in[13];
    const float* gru_w_hh  = (const float*)d_in[14];
    const float* gru_b_ih  = (const float*)d_in[15];
    const float* gru_b_hh  = (const float*)d_in[16];
    float* out = (float*)d_out;

    int N_ = in_sizes[0] / DD;
    int M_ = in_sizes[1] / 2;

    cudaFuncSetAttribute(edge_kernel, cudaFuncAttributeMaxDynamicSharedMemorySize,
                         EDGE_SMEM_BYTES);

    size_t tot = (size_t)N_ * DD;
    zero_agg_kernel<<<(int)((tot + 255) / 256), 256>>>();

    int nblocks = (N_ + 63) / 64;
    nodeproj_kernel<<<nblocks, NTHREADS>>>(node_feat, node_attr, edge_attr,
                                           msg_w1, att_w1, N_);

    int ntiles = (M_ + 63) / 64;
    // 4 sequential quarter launches (profiling visibility + identical total work)
    for (int q = 0; q < 4; ++q) {
        int t0 = (ntiles * q) / 4;
        int t1 = (ntiles * (q + 1)) / 4;
        int nt = t1 - t0;
        if (nt <= 0) continue;
        int egrid = nt < 148 ? nt : 148;
        edge_kernel<<<egrid, ETH, EDGE_SMEM_BYTES>>>(
            edge, edge_feat,
            msg_w1, msg_b1, msg_w2, msg_b2,
            att_w1, att_b1, att_w2, att_b2, M_, t0, t1);
    }

    int gblocks = (N_ + 7) / 8;
    gru_kernel<<<gblocks, 128>>>(node_feat, gru_w_ih, gru_w_hh, gru_b_ih, gru_b_hh, out, N_);
}